// round 6
// baseline (speedup 1.0000x reference)
#include <cuda_runtime.h>
#include <cuda_bf16.h>

// y = (x + 2) * 3 / 2 == fmaf(1.5f, x, 3.0f)
// HBM-bound streaming kernel. R6: R2 shape (flat grid, 128B/thread, 256 thr,
// 32-bit idx, streaming hints) using Blackwell 256-bit vector ld/st
// (ld/st.global.v8.f32 -> LDG.E.256 / STG.E.256): half the LSU transactions
// per byte vs float4.

constexpr int V8PT = 4;                  // 8-float (32B) vectors per thread
constexpr int THREADS = 256;
constexpr int TILE_FLOATS = V8PT * THREADS * 8;   // 8192 floats per block

__device__ __forceinline__ void ld256_cs(const float* p, float r[8]) {
    asm volatile(
        "ld.global.cs.v8.f32 {%0,%1,%2,%3,%4,%5,%6,%7}, [%8];"
        : "=f"(r[0]), "=f"(r[1]), "=f"(r[2]), "=f"(r[3]),
          "=f"(r[4]), "=f"(r[5]), "=f"(r[6]), "=f"(r[7])
        : "l"(p));
}

__device__ __forceinline__ void st256_cs(float* p, const float r[8]) {
    asm volatile(
        "st.global.cs.v8.f32 [%0], {%1,%2,%3,%4,%5,%6,%7,%8};"
        :: "l"(p),
           "f"(r[0]), "f"(r[1]), "f"(r[2]), "f"(r[3]),
           "f"(r[4]), "f"(r[5]), "f"(r[6]), "f"(r[7])
        : "memory");
}

__global__ void __launch_bounds__(THREADS) fma_stream_kernel(
    const float* __restrict__ in, float* __restrict__ out)
{
    // thread's first vector: 32B-aligned, warp covers 1024B contiguous
    unsigned base = blockIdx.x * TILE_FLOATS + threadIdx.x * 8u;

    float v[V8PT][8];
#pragma unroll
    for (int k = 0; k < V8PT; k++)
        ld256_cs(in + base + (unsigned)k * THREADS * 8u, v[k]);

#pragma unroll
    for (int k = 0; k < V8PT; k++) {
        float r[8];
#pragma unroll
        for (int j = 0; j < 8; j++)
            r[j] = fmaf(1.5f, v[k][j], 3.0f);
        st256_cs(out + base + (unsigned)k * THREADS * 8u, r);
    }
}

// Generic remainder kernel (element granularity, any size).
__global__ void fma_tail_kernel(const float* __restrict__ in,
                                float* __restrict__ out,
                                long long start, long long n)
{
    long long i = start + (long long)blockIdx.x * blockDim.x + threadIdx.x;
    if (i < n) out[i] = fmaf(1.5f, in[i], 3.0f);
}

extern "C" void kernel_launch(void* const* d_in, const int* in_sizes, int n_in,
                              void* d_out, int out_size)
{
    const float* in = (const float*)d_in[0];
    float* out = (float*)d_out;
    long long n = (long long)in_sizes[0];

    long long full_blocks = n / TILE_FLOATS;
    if (full_blocks > 0) {
        fma_stream_kernel<<<(unsigned)full_blocks, THREADS>>>(in, out);
    }
    long long done = full_blocks * (long long)TILE_FLOATS;
    long long tail = n - done;
    if (tail > 0) {
        fma_tail_kernel<<<(unsigned)((tail + 255) / 256), 256>>>(
            in, out, done, n);
    }
}

// round 7
// speedup vs baseline: 1.0012x; 1.0012x over previous
#include <cuda_runtime.h>
#include <cuda_bf16.h>

// y = (x + 2) * 3 / 2 == fmaf(1.5f, x, 3.0f)
// HBM-bound streaming kernel. R7: finer block granularity (VPT=4 -> 16 KB
// per block, 16384 blocks) to shrink the straggler tail / improve HW
// work-steal rebalance granularity. Flat grid, front-batched float4 loads,
// 32-bit indexing, streaming cache hints.

constexpr int VPT = 4;                 // float4 per thread (64 B/thread)
constexpr int THREADS = 256;
constexpr int TILE = VPT * THREADS;    // float4 per block = 1024 (16 KB)

__global__ void __launch_bounds__(THREADS) fma_stream_kernel(
    const float4* __restrict__ in, float4* __restrict__ out)
{
    unsigned base = blockIdx.x * TILE + threadIdx.x;

    float4 v[VPT];
#pragma unroll
    for (int k = 0; k < VPT; k++)
        v[k] = __ldcs(in + base + k * THREADS);

#pragma unroll
    for (int k = 0; k < VPT; k++) {
        float4 r;
        r.x = fmaf(1.5f, v[k].x, 3.0f);
        r.y = fmaf(1.5f, v[k].y, 3.0f);
        r.z = fmaf(1.5f, v[k].z, 3.0f);
        r.w = fmaf(1.5f, v[k].w, 3.0f);
        __stcs(out + base + k * THREADS, r);
    }
}

// Generic remainder kernel (element granularity, any size).
__global__ void fma_tail_kernel(const float* __restrict__ in,
                                float* __restrict__ out,
                                long long start, long long n)
{
    long long i = start + (long long)blockIdx.x * blockDim.x + threadIdx.x;
    if (i < n) out[i] = fmaf(1.5f, in[i], 3.0f);
}

extern "C" void kernel_launch(void* const* d_in, const int* in_sizes, int n_in,
                              void* d_out, int out_size)
{
    const float* in = (const float*)d_in[0];
    float* out = (float*)d_out;
    long long n = (long long)in_sizes[0];

    long long n4 = n / 4;
    long long full_blocks = n4 / TILE;
    if (full_blocks > 0) {
        fma_stream_kernel<<<(unsigned)full_blocks, THREADS>>>(
            (const float4*)in, (float4*)out);
    }
    long long done = full_blocks * (long long)TILE * 4;  // elements handled
    long long tail = n - done;
    if (tail > 0) {
        fma_tail_kernel<<<(unsigned)((tail + 255) / 256), 256>>>(
            in, out, done, n);
    }
}